// round 16
// baseline (speedup 1.0000x reference)
#include <cuda_runtime.h>

// ---------------- problem constants ----------------
#define C_CH   256
#define H_BEV  200
#define W_BEV  704
#define HW     (H_BEV * W_BEV)     // 140800
#define A_NUM  2
#define NC_NUM 4
#define K_SEL  20000
#define NSLOT  (A_NUM * HW)        // 281600 flat A*H*W cells
#define RM_OFF NSLOT               // rm starts after psm in d_out
#define CTA_PX 128                 // pixels per block (1 px per thread)
#define THREADS 128                // 4 warps x 32 px each
#define CHUNK  8                   // channels per pipeline stage == K per mma
#define NSTAGE 6                   // pipeline depth
#define NCHUNK (C_CH / CHUNK)      // 32
#define ROWSTRIDE 136              // floats per staged row (128 px + 8 pad)
#define ROWB   (ROWSTRIDE * 4)     // 544 bytes
#define STAGE_BYTES (CHUNK * ROWB) // 4352
#define CBSTRIDE 130               // cbuf row stride (floats), even for f2 stores

// packed winner table: high32 = float bits of peer score (positive -> monotonic),
// low32 = ((3 - cav_idx) << 16) | k.  0 == no peer selected this cell.
__device__ __align__(16) unsigned long long g_slots[NSLOT];

// ---------------- helpers ----------------
__device__ __forceinline__ unsigned long long pack2(float lo, float hi) {
    unsigned long long r;
    asm("mov.b64 %0, {%1, %2};" : "=l"(r) : "f"(lo), "f"(hi));
    return r;
}
__device__ __forceinline__ void unpack2(unsigned long long v, float& lo, float& hi) {
    asm("mov.b64 {%0, %1}, %2;" : "=f"(lo), "=f"(hi) : "l"(v));
}
__device__ __forceinline__ unsigned long long fma2(unsigned long long a,
                                                   unsigned long long b,
                                                   unsigned long long c) {
    asm("fma.rn.f32x2 %0, %1, %2, %3;" : "=l"(c) : "l"(a), "l"(b), "l"(c));
    return c;
}
__device__ __forceinline__ unsigned cvt_tf32(float x) {
    unsigned u;
    asm("cvt.rna.tf32.f32 %0, %1;" : "=r"(u) : "f"(x));
    return u;
}
__device__ __forceinline__ void cp_async16(unsigned smem_dst, const void* gsrc) {
    asm volatile("cp.async.cg.shared.global [%0], [%1], 16;\n"
                 :: "r"(smem_dst), "l"(gsrc));
}
__device__ __forceinline__ void mma_tf32(float& d0, float& d1, float& d2, float& d3,
                                         unsigned a0, unsigned a1, unsigned a2, unsigned a3,
                                         unsigned b0, unsigned b1) {
    asm volatile("mma.sync.aligned.m16n8k8.row.col.f32.tf32.tf32.f32 "
                 "{%0,%1,%2,%3}, {%4,%5,%6,%7}, {%8,%9}, {%0,%1,%2,%3};\n"
                 : "+f"(d0), "+f"(d1), "+f"(d2), "+f"(d3)
                 : "r"(a0), "r"(a1), "r"(a2), "r"(a3), "r"(b0), "r"(b1));
}

// ---------------- kernel 1: scatter peer candidates ----------------
__global__ void k_scatter(const int* __restrict__ mask_idx,
                          const float* __restrict__ scores) {
    int t = blockIdx.x * blockDim.x + threadIdx.x;
    if (t >= NC_NUM * K_SEL) return;
    int i = t / K_SEL;
    int k = t - i * K_SEL;                       // k < 20000 < 2^16
    int f = mask_idx[t];                         // flat index in [0, A*H*W)
    unsigned long long key =
        ((unsigned long long)__float_as_uint(scores[t]) << 32) |
        ((unsigned long long)(3 - i) << 16) | (unsigned)k;
    atomicMax(&g_slots[f], key);
}

// ---------------- kernel 2: tf32 tensor-core heads + exact fp32 cls --------
// 128 threads = 4 warps x 32 px.  grid = 1100 blocks exactly.
__global__ __launch_bounds__(THREADS)
void k_main(const float*  __restrict__ feat,     // [C, HW] f32
            const float*  __restrict__ cls_w,    // [2, 256]
            const float*  __restrict__ cls_b,    // [2]
            const float*  __restrict__ reg_w,    // [14, 256]
            const float*  __restrict__ reg_b,    // [14]
            const float*  __restrict__ psm_v2x,  // [4, 20000]
            const float*  __restrict__ rm_v2x,   // [4, 7*20000]
            float*        __restrict__ out) {    // [psm 281600 | rm 1971200]
    // A fragments (tf32 weights) pre-laid out: wfragA[k][lane][r] -> LDS.128
    __shared__ __align__(16) unsigned wfragA[NCHUNK][32][4];          // 16384 B
    __shared__ __align__(8)  float2   wcls2[C_CH];                    // 2048 B
    __shared__ __align__(16) float    fbuf[NSTAGE][CHUNK][ROWSTRIDE]; // 26112 B
    // total static smem = 44544 B; fbuf reused as cbuf[16][130] after the loop

    const int tid    = threadIdx.x;
    const int lane   = tid & 31;
    const int warp   = tid >> 5;
    const int g      = lane >> 2;        // groupID
    const int t4     = lane & 3;         // threadID_in_group
    const int pxW    = warp * 32;        // warp's pixel base within block
    const int pxBase = blockIdx.x * CTA_PX;

    unsigned fbuf_s = (unsigned)__cvta_generic_to_shared(&fbuf[0][0][0]);
    const int crow = tid >> 5;           // copy row base (0..3); rows crow, crow+4
    const int cseg = tid & 31;           // 16B segment within row

    // ---- prologue: launch chunks 0..4 into slots 0..4 ----
#pragma unroll
    for (int b = 0; b < NSTAGE - 1; ++b) {
        unsigned dst = fbuf_s + (unsigned)b * STAGE_BYTES + (unsigned)crow * ROWB + cseg * 16;
        const float* src = feat + (size_t)(b * CHUNK + crow) * HW + pxBase + cseg * 4;
        cp_async16(dst, src);
        cp_async16(dst + 4 * ROWB, src + (size_t)4 * HW);
        asm volatile("cp.async.commit_group;\n");
    }

    // ---- weight fills overlap with the first copies ----
    // A fragments: wfragA[k][lane][r] = tf32(W[row][ch]),
    //   row = g + 8*(r&1), ch = k*8 + t4 + 4*(r>>1)
    for (int i = tid; i < NCHUNK * 32 * 4; i += THREADS) {
        int k = i >> 7, rem = i & 127;
        int ln = rem >> 2, r = rem & 3;
        int gg = ln >> 2, tt = ln & 3;
        int row = gg + 8 * (r & 1);
        int ch  = k * CHUNK + tt + 4 * (r >> 1);
        float w = (row < A_NUM) ? cls_w[row * C_CH + ch]
                                : reg_w[(row - A_NUM) * C_CH + ch];
        wfragA[k][ln][r] = cvt_tf32(w);
    }
    // exact fp32 cls weights, pairs (cls0[c], cls1[c])
    for (int c = tid; c < C_CH; c += THREADS)
        wcls2[c] = make_float2(cls_w[c], cls_w[C_CH + c]);

    // accumulators
    float d[4][4];                       // 4 n8-tiles x 4 C regs (16 outs x 32 px)
#pragma unroll
    for (int tt = 0; tt < 4; ++tt)
#pragma unroll
        for (int r = 0; r < 4; ++r) d[tt][r] = 0.0f;
    unsigned long long accC = 0ULL;      // exact fp32 (cls0, cls1) for px = tid

    // ---- main loop: wait chunk k, barrier, issue chunk k+5, compute k ----
    for (int k = 0; k < NCHUNK; ++k) {
        asm volatile("cp.async.wait_group %0;\n" :: "n"(NSTAGE - 2));
        __syncthreads();                 // chunk k visible to all threads

        if (k + NSTAGE - 1 < NCHUNK) {   // copy chunk k+5 into slot (k-1)%6
            int nk = k + NSTAGE - 1;
            unsigned dst = fbuf_s + (unsigned)(nk % NSTAGE) * STAGE_BYTES
                         + (unsigned)crow * ROWB + cseg * 16;
            const float* src = feat + (size_t)(nk * CHUNK + crow) * HW + pxBase + cseg * 4;
            cp_async16(dst, src);
            cp_async16(dst + 4 * ROWB, src + (size_t)4 * HW);
        }
        asm volatile("cp.async.commit_group;\n");   // keep group count in step

        const int slot = k % NSTAGE;
        const float* fb = &fbuf[slot][0][0];

        // exact fp32 cls accumulation for this thread's pixel (px = tid)
#pragma unroll
        for (int c = 0; c < CHUNK; ++c) {
            float x = fb[c * ROWSTRIDE + tid];               // LDS.32 conflict-free
            float2 w = wcls2[k * CHUNK + c];                 // broadcast LDS.64
            accC = fma2(pack2(x, x), pack2(w.x, w.y), accC);
        }

        // A fragment for this k-step: one LDS.128
        uint4 av = *(const uint4*)&wfragA[k][lane][0];

        // 4 n8 pixel tiles
#pragma unroll
        for (int tt = 0; tt < 4; ++tt) {
            int px0 = pxW + tt * 8 + g;
            unsigned b0 = cvt_tf32(fb[t4 * ROWSTRIDE + px0]);        // B[k=t4][n]
            unsigned b1 = cvt_tf32(fb[(t4 + 4) * ROWSTRIDE + px0]);  // B[k=t4+4][n]
            mma_tf32(d[tt][0], d[tt][1], d[tt][2], d[tt][3],
                     av.x, av.y, av.z, av.w, b0, b1);
        }
    }

    // ---- redistribute accumulators via smem (alias drained fbuf) ----
    __syncthreads();                     // all fbuf reads done; safe to alias
    float* cbuf = &fbuf[0][0][0];        // cbuf[16][CBSTRIDE]
#pragma unroll
    for (int tt = 0; tt < 4; ++tt) {
        int px0 = pxW + tt * 8 + 2 * t4;                     // even -> f2 aligned
        *(float2*)&cbuf[g * CBSTRIDE + px0]       = make_float2(d[tt][0], d[tt][1]);
        *(float2*)&cbuf[(g + 8) * CBSTRIDE + px0] = make_float2(d[tt][2], d[tt][3]);
    }
    __syncthreads();

    // ---- epilogue: 1 px per thread, all 16 outs ----
    int p = pxBase + tid;
    float clsv0, clsv1;
    unpack2(accC, clsv0, clsv1);
    float clsv[2] = {clsv0, clsv1};

#pragma unroll
    for (int a = 0; a < A_NUM; ++a) {
        int f = a * HW + p;
        float psm_ego = clsv[a] + cls_b[a];                  // exact fp32
        float prob    = 1.0f / (1.0f + expf(-psm_ego));      // sigmoid, fp32

        unsigned long long key = g_slots[f];                 // coalesced LDG.64
        bool peer = false;
        int ci = 0, ck = 0;
        if (key != 0ULL) {
            float s = __uint_as_float((unsigned)(key >> 32));
            if (s > prob) {                  // strict >: ego wins ties (argmax first-max)
                peer = true;
                unsigned lo = (unsigned)key;
                ck = (int)(lo & 0xFFFFu);
                ci = 3 - (int)((lo >> 16) & 0xFFFFu);
            }
        }

        out[f] = peer ? psm_v2x[ci * K_SEL + ck] : psm_ego;

#pragma unroll
        for (int r = 0; r < 7; ++r) {
            int rc = 2 * r + a;              // rm channel using anchor-a winner
            float ego = cbuf[(2 + rc) * CBSTRIDE + tid] + reg_b[rc];
            out[RM_OFF + rc * HW + p] =
                peer ? rm_v2x[(ci * 7 + r) * K_SEL + ck] : ego;
        }
    }
}

// ---------------- launch ----------------
extern "C" void kernel_launch(void* const* d_in, const int* in_sizes, int n_in,
                              void* d_out, int out_size) {
    const float*  feat     = (const float*)d_in[0];   // [1,256,200,704] f32
    const float*  cls_w    = (const float*)d_in[1];   // [2,256]
    const float*  cls_b    = (const float*)d_in[2];   // [2]
    const float*  reg_w    = (const float*)d_in[3];   // [14,256]
    const float*  reg_b    = (const float*)d_in[4];   // [14]
    const float*  psm_v2x  = (const float*)d_in[5];   // [4,20000]
    const float*  rm_v2x   = (const float*)d_in[6];   // [4,140000]
    const float*  scores   = (const float*)d_in[7];   // [4,20000]
    const int*    mask_idx = (const int*)d_in[8];     // [4,20000]
    // d_in[9] = mask_reg_idx: derivable (f + r*A*H*W), unused.
    float* out = (float*)d_out;

    // zero the winner table via a graph memset node (no kernel launch cost)
    void* slots_ptr = nullptr;
    cudaGetSymbolAddress(&slots_ptr, g_slots);
    cudaMemsetAsync(slots_ptr, 0, NSLOT * sizeof(unsigned long long));

    k_scatter<<<(NC_NUM * K_SEL + 255) / 256, 256>>>(mask_idx, scores);

    k_main<<<HW / CTA_PX, THREADS>>>(feat, cls_w, cls_b, reg_w, reg_b,
                                     psm_v2x, rm_v2x, out);
}